// round 9
// baseline (speedup 1.0000x reference)
#include <cuda_runtime.h>
#include <cuda_bf16.h>
#include <cstdint>

#define TILE_H 8
#define TILE_W 32
#define HALO_H (TILE_H + 2)        // 10
#define ROWSPAN 40                 // padded row: gmem cols [tw0-4, tw0+36), 160B aligned
#define PLANE  (HALO_H * ROWSPAN)  // 400 floats per channel plane
#define CCH    64
#define HH     128
#define WWD    128
#define HW     (HH * WWD)
#define NTAP   9
#define WSTRIDE 12                 // 9 weights padded to 12 floats for aligned 16B loads
#define CHUNK  8
#define NCHUNK (CCH / CHUNK)       // 8
#define NSLOT4 (CHUNK * HALO_H * 10)   // 800 float4 slots per chunk staging

#define XS_ELEMS (CHUNK * PLANE)             // 3200 floats per buffer
#define WS_ELEMS (NTAP * CCH * WSTRIDE)      // 6912
#define SMEM_BYTES ((2 * XS_ELEMS + WS_ELEMS) * 4)  // 53248 B -> occ-3 by smem

extern __shared__ float smem[];

typedef unsigned long long u64t;

#define CP_COMMIT() asm volatile("cp.async.commit_group;\n" ::: "memory")
#define CP_WAIT0()  asm volatile("cp.async.wait_group 0;\n" ::: "memory")

__device__ __forceinline__ u64t pack2(float lo, float hi) {
    u64t r;
    asm("mov.b64 %0, {%1, %2};" : "=l"(r) : "r"(__float_as_uint(lo)), "r"(__float_as_uint(hi)));
    return r;
}
__device__ __forceinline__ u64t dup2(float v) {
    u64t r;
    asm("mov.b64 %0, {%1, %1};" : "=l"(r) : "r"(__float_as_uint(v)));
    return r;
}
// d = a*b + c elementwise on packed f32x2 -> single FFMA2 in SASS
__device__ __forceinline__ u64t ffma2(u64t a, u64t b, u64t c) {
    u64t d;
    asm("fma.rn.f32x2 %0, %1, %2, %3;" : "=l"(d) : "l"(a), "l"(b), "l"(c));
    return d;
}

// One 8-channel chunk = 800 aligned float4 copies; 4 slots/thread (last partial),
// descriptors precomputed once. Invalid slots zero-fill via cp.async src-size=0,
// which also writes the conv's zero halo at image borders.
__device__ __forceinline__ void stage_async(float* __restrict__ buf,
                                            const float* __restrict__ xc,
                                            const int* __restrict__ goff,
                                            int tid)
{
    uint32_t sa = (uint32_t)__cvta_generic_to_shared(buf) + (uint32_t)tid * 16u;
    #pragma unroll
    for (int s = 0; s < 3; ++s) {
        const int o = goff[s];
        const float* src = xc + (o >= 0 ? o : 0);
        const int z = (o >= 0) ? 16 : 0;
        asm volatile("cp.async.cg.shared.global [%0], [%1], 16, %2;\n"
                     :: "r"(sa + (uint32_t)s * 4096u), "l"(src), "r"(z) : "memory");
    }
    if (tid < (NSLOT4 - 3 * 256)) {   // tid < 32
        const int o = goff[3];
        const float* src = xc + (o >= 0 ? o : 0);
        const int z = (o >= 0) ? 16 : 0;
        asm volatile("cp.async.cg.shared.global [%0], [%1], 16, %2;\n"
                     :: "r"(sa + 3u * 4096u), "l"(src), "r"(z) : "memory");
    }
}

__global__ __launch_bounds__(256, 3)
void ahpf_fused_kernel(const float* __restrict__ x,
                       const float* __restrict__ Wt,
                       const float* __restrict__ bias,
                       float* __restrict__ out)
{
    float* xsA = smem;                         // buffer 0: [8][10][40]
    float* xsB = smem + XS_ELEMS;              // buffer 1
    float* ws  = smem + 2 * XS_ELEMS;          // [tap][c][12], k contiguous
    float* xbuf[2] = { xsA, xsB };

    const int tw0 = blockIdx.x * TILE_W;
    const int th0 = blockIdx.y * TILE_H;
    const int b   = blockIdx.z;
    const int tid = threadIdx.x;

    // --- Precompute float4 staging descriptors (4 slots/thread, reused 15x) ---
    int goff[4];
    #pragma unroll
    for (int s = 0; s < 4; ++s) {
        const int i = tid + 256 * s;
        int o = -1;
        if (i < NSLOT4) {
            const int chan = i / 100;          // 100 float4 per channel plane
            const int p    = i - chan * 100;
            const int r    = p / 10;           // halo row 0..9
            const int g    = p - r * 10;       // 4-col group 0..9
            const int row  = th0 - 1 + r;
            const int col  = tw0 - 4 + 4 * g;  // group fully in or out (4 | tw0)
            if (row >= 0 && row < HH && col >= 0 && col < WWD)
                o = chan * HW + row * WWD + col;
        }
        goff[s] = o;
    }

    const float* xb = x + (size_t)b * CCH * HW;

    // --- Prologue: start chunk 0 copy, stage weights meanwhile ---
    stage_async(xbuf[0], xb, goff, tid);
    CP_COMMIT();

    // ws[(tap*64 + c)*12 + k] = W[k][c][tap]
    for (int i = tid; i < NTAP * CCH * NTAP; i += 256) {
        int k   = i / (CCH * NTAP);
        int rem = i - k * (CCH * NTAP);
        int c   = rem / NTAP;
        int tap = rem - c * NTAP;
        ws[(tap * CCH + c) * WSTRIDE + k] = Wt[(k * CCH + c) * NTAP + tap];
    }

    const int w  = tid & 31;
    const int h  = tid >> 5;             // 0..7, one pixel per thread
    const int gh = th0 + h;
    const int gw = tw0 + w;

    // Packed accumulators: k-pairs (0,1)(2,3)(4,5)(6,7) + scalar k=8
    u64t accA[4];
    float acc8;
    #pragma unroll
    for (int j = 0; j < 4; ++j) accA[j] = pack2(bias[2 * j], bias[2 * j + 1]);
    acc8 = bias[8];

    CP_WAIT0();
    __syncthreads();

    // ---------------- Conv via FFMA2: 9 logits per pixel -------------------------
    for (int ch = 0; ch < NCHUNK; ++ch) {
        if (ch + 1 < NCHUNK) {
            stage_async(xbuf[(ch + 1) & 1], xb + (size_t)(ch + 1) * CHUNK * HW, goff, tid);
            CP_COMMIT();
        }

        const float* xsc = xbuf[ch & 1];
        #pragma unroll 2
        for (int c = 0; c < CHUNK; ++c) {
            // 3x3 neighborhood of this pixel (halo rows h..h+2)
            const float* xr = xsc + c * PLANE + h * ROWSPAN + (w + 3);
            float xv[3][3];
            #pragma unroll
            for (int r = 0; r < 3; ++r)
                #pragma unroll
                for (int j = 0; j < 3; ++j)
                    xv[r][j] = xr[r * ROWSPAN + j];

            const float* wc = ws + (ch * CHUNK + c) * WSTRIDE;
            #pragma unroll
            for (int di = 0; di < 3; ++di) {
                #pragma unroll
                for (int dj = 0; dj < 3; ++dj) {
                    const float* wq = wc + ((di * 3 + dj) * CCH) * WSTRIDE;
                    const ulonglong2 wp0 = *reinterpret_cast<const ulonglong2*>(wq);
                    const ulonglong2 wp1 = *reinterpret_cast<const ulonglong2*>(wq + 4);
                    const float      w8  = wq[8];
                    const float a0 = xv[di][dj];
                    const u64t a0d = dup2(a0);
                    accA[0] = ffma2(a0d, wp0.x, accA[0]);
                    accA[1] = ffma2(a0d, wp0.y, accA[1]);
                    accA[2] = ffma2(a0d, wp1.x, accA[2]);
                    accA[3] = ffma2(a0d, wp1.y, accA[3]);
                    acc8    = fmaf(a0, w8, acc8);
                }
            }
        }

        if (ch + 1 < NCHUNK) CP_WAIT0();
        __syncthreads();
    }

    // Unpack accumulators
    float acc[NTAP];
    #pragma unroll
    for (int j = 0; j < 4; ++j) {
        float2 fa = *reinterpret_cast<float2*>(&accA[j]);
        acc[2 * j] = fa.x; acc[2 * j + 1] = fa.y;
    }
    acc[8] = acc8;

    // ---------------- softmax * hamming, renormalized (denominator cancels) -----
    const float hamv[NTAP] = {0.0064f, 0.08f, 0.0064f,
                              0.08f,   1.0f,  0.08f,
                              0.0064f, 0.08f, 0.0064f};
    float mask[NTAP];
    {
        float mx = acc[0];
        #pragma unroll
        for (int k = 1; k < NTAP; ++k) mx = fmaxf(mx, acc[k]);
        float s = 0.f;
        #pragma unroll
        for (int k = 0; k < NTAP; ++k) {
            float e = __expf(acc[k] - mx) * hamv[k];
            mask[k] = e;
            s += e;
        }
        const float inv = __fdividef(1.f, s);
        #pragma unroll
        for (int k = 0; k < NTAP; ++k) mask[k] *= inv;
    }

    // ---------------- reflect-padded offsets -------------------------------------
    int roff[3], coff[3];
    #pragma unroll
    for (int i = 0; i < 3; ++i) {
        int g = gh - 1 + i;
        g = (g < 0) ? 1 : ((g >= HH) ? (HH - 2) : g);
        roff[i] = (g - th0 + 1) * ROWSPAN;
    }
    #pragma unroll
    for (int j = 0; j < 3; ++j) {
        int g = gw - 1 + j;
        g = (g < 0) ? 1 : ((g >= WWD) ? (WWD - 2) : g);
        coff[j] = g - tw0 + 4;
    }

    // ---------------- CARAFE lowpass + highpass residual ------------------------
    // Reverse walk: chunk NCHUNK-1 is still resident in buf[(NCHUNK-1)&1].
    float* outb = out + ((size_t)b * CCH) * HW + (size_t)gh * WWD + gw;

    for (int chr = 0; chr < NCHUNK; ++chr) {
        const int ch = NCHUNK - 1 - chr;
        if (ch > 0) {
            stage_async(xbuf[(ch - 1) & 1], xb + (size_t)(ch - 1) * CHUNK * HW, goff, tid);
            CP_COMMIT();
        }

        const float* xsc = xbuf[ch & 1];
        #pragma unroll 2
        for (int c = 0; c < CHUNK; ++c) {
            const float* xc = xsc + c * PLANE;
            float v[3][3];
            #pragma unroll
            for (int i = 0; i < 3; ++i)
                #pragma unroll
                for (int j = 0; j < 3; ++j)
                    v[i][j] = xc[roff[i] + coff[j]];

            // v[1][1] = this pixel's center (row gh, col gw; never reflected)
            float lp = mask[0] * v[0][0];
            #pragma unroll
            for (int k = 1; k < NTAP; ++k)
                lp = fmaf(mask[k], v[k / 3][k % 3], lp);

            outb[(size_t)(ch * CHUNK + c) * HW] = 2.f * v[1][1] - lp;
        }

        if (ch > 0) {
            CP_WAIT0();
            __syncthreads();
        }
    }
}

extern "C" void kernel_launch(void* const* d_in, const int* in_sizes, int n_in,
                              void* d_out, int out_size)
{
    const float* x  = (const float*)d_in[0];
    const float* Wt = (const float*)d_in[1];
    const float* bs = (const float*)d_in[2];
    float* out = (float*)d_out;

    const int B = in_sizes[0] / (CCH * HW);

    cudaFuncSetAttribute(ahpf_fused_kernel,
                         cudaFuncAttributeMaxDynamicSharedMemorySize, SMEM_BYTES);

    dim3 grid(WWD / TILE_W, HH / TILE_H, B);
    ahpf_fused_kernel<<<grid, 256, SMEM_BYTES>>>(x, Wt, bs, out);
}